// round 4
// baseline (speedup 1.0000x reference)
#include <cuda_runtime.h>
#include <cstdint>
#include <cstddef>

#define LOG2E_F 1.4426950408889634f
#define LN2_F   0.6931471805599453f

__device__ __forceinline__ float ex2f_(float x) {
    float y; asm("ex2.approx.ftz.f32 %0, %1;" : "=f"(y) : "f"(x)); return y;
}
__device__ __forceinline__ float lg2f_(float x) {
    float y; asm("lg2.approx.f32 %0, %1;" : "=f"(y) : "f"(x)); return y;
}
__device__ __forceinline__ unsigned long long pk2(float lo, float hi) {
    unsigned long long r; asm("mov.b64 %0, {%1, %2};" : "=l"(r) : "f"(lo), "f"(hi)); return r;
}
__device__ __forceinline__ void upk2(unsigned long long v, float& lo, float& hi) {
    asm("mov.b64 {%0, %1}, %2;" : "=f"(lo), "=f"(hi) : "l"(v));
}
__device__ __forceinline__ void fma2_(unsigned long long& acc, unsigned long long a, unsigned long long b) {
    asm("fma.rn.f32x2 %0, %1, %2, %0;" : "+l"(acc) : "l"(a), "l"(b));
}
__device__ __forceinline__ unsigned long long add2_(unsigned long long a, unsigned long long b) {
    unsigned long long r; asm("add.rn.f32x2 %0, %1, %2;" : "=l"(r) : "l"(a), "l"(b)); return r;
}

// One CTA per batch, 256 threads. cp = tid>>2 -> column pair (j0=2cp, j0+1),
// ich = tid&3 -> 32-wide "from"-state chunk. E = exp(logA) in registers as
// i-pair packed f32x2 operands. Forward vector linear-domain in
// double-buffered smem (chunk stride 36 floats -> LDS.128, conflict-free,
// ulonglong2 halves feed fma.rn.f32x2 directly). Exact power-of-2 renorm every
// 8 steps, statically scheduled in an 8-step unrolled group (fold at pos 0,
// REDUX publish at pos 7) -> 6 of 8 steps carry zero renorm code. One
// __syncthreads per step. obs streamed via an 8-deep register prefetch ring.
__global__ __launch_bounds__(256, 1)
void crf_fwd_kernel(const float* __restrict__ obs,
                    const float* __restrict__ logA,
                    float* __restrict__ out,
                    int T)
{
    constexpr int S = 128;
    constexpr int CH = 36;                         // chunk stride (floats): 16B-aligned, bank-skewed
    __shared__ __align__(16) float v_sm[2][4 * CH];
    __shared__ float wm[8];
    __shared__ float wsum[4];

    const int tid  = threadIdx.x;
    const int b    = blockIdx.x;
    const int cp   = tid >> 2;
    const int ich  = tid & 3;
    const int j0   = cp * 2;
    const int warp = tid >> 5;
    const int wslot = ((j0 >> 5) * CH) + (j0 & 31);

    const float* ob = obs + (size_t)b * (size_t)T * S + j0;

    // A0[k] = {E[i0+2k][j0],   E[i0+2k+1][j0]}
    // A1[k] = {E[i0+2k][j0+1], E[i0+2k+1][j0+1]},  i0 = 32*ich
    unsigned long long A0[16], A1[16];
#pragma unroll
    for (int k = 0; k < 16; ++k) {
        const int i0 = ich * 32 + 2 * k;
        const float2 ea = *reinterpret_cast<const float2*>(logA + (size_t)i0 * S + j0);
        const float2 eb = *reinterpret_cast<const float2*>(logA + (size_t)(i0 + 1) * S + j0);
        A0[k] = pk2(ex2f_(ea.x * LOG2E_F), ex2f_(eb.x * LOG2E_F));
        A1[k] = pk2(ex2f_(ea.y * LOG2E_F), ex2f_(eb.y * LOG2E_F));
    }

    // ---- t = 0 (t%8==0): u = exp(obs[0]) raw; publish block max ----
    const float2 o0 = *reinterpret_cast<const float2*>(ob);
    const float u0 = ex2f_(o0.x * LOG2E_F);
    const float u1 = ex2f_(o0.y * LOG2E_F);
    {
        const int im = __reduce_max_sync(0xffffffffu, __float_as_int(fmaxf(u0, u1)));
        if ((tid & 31) == 0) wm[warp] = __int_as_float(im);
        if (ich == 0) {
            float2 w; w.x = u0; w.y = u1;
            *reinterpret_cast<float2*>(&v_sm[0][wslot]) = w;
        }
    }

    // 8-deep obs prefetch ring: oR[t & 7] holds obs[t].
    float2 oR[8];
#pragma unroll
    for (int k = 1; k <= 8; ++k)
        oR[k & 7] = (k < T) ? __ldcs(reinterpret_cast<const float2*>(ob + (size_t)k * S)) : o0;

    int L = 0;                 // exact accumulated log2 scale (uniform across block)
    __syncthreads();

    // One scan step. POS: static position in the 8-group (t = t0 + POS).
    // CBUF = (t-1)&1 read buffer. FOLD: apply 2^-e from last publish.
    // PUB: publish block max for the next fold.
#define CRF_STEP(T_CUR, CBUF, FOLD, PUB)                                          \
    {                                                                              \
        const int t_ = (T_CUR);                                                    \
        const float2 oc = oR[t_ & 7];                                              \
        if (t_ + 8 < T)                                                            \
            oR[t_ & 7] = __ldcs(reinterpret_cast<const float2*>(ob + (size_t)(t_ + 8) * S)); \
        const float p0 = ex2f_(oc.x * LOG2E_F);                                    \
        const float p1 = ex2f_(oc.y * LOG2E_F);                                    \
        float sc_ = 1.0f;                                                          \
        if (FOLD) {                                                                \
            const float m = fmaxf(fmaxf(fmaxf(wm[0], wm[1]), fmaxf(wm[2], wm[3])), \
                                  fmaxf(fmaxf(wm[4], wm[5]), fmaxf(wm[6], wm[7])));\
            const int e = ((__float_as_int(m) >> 23) & 0xFF) - 127;                \
            L += e;                                                                \
            sc_ = __int_as_float((127 - e) << 23);                                 \
        }                                                                          \
        const ulonglong2* V =                                                      \
            reinterpret_cast<const ulonglong2*>(&v_sm[CBUF][ich * CH]);            \
        unsigned long long c0a = 0ull, c0b = 0ull, c1a = 0ull, c1b = 0ull;         \
        _Pragma("unroll")                                                          \
        for (int k = 0; k < 8; ++k) {                                              \
            const ulonglong2 vv = V[k];                                            \
            fma2_(c0a, vv.x, A0[2 * k]);                                           \
            fma2_(c1a, vv.x, A1[2 * k]);                                           \
            fma2_(c0b, vv.y, A0[2 * k + 1]);                                       \
            fma2_(c1b, vv.y, A1[2 * k + 1]);                                       \
        }                                                                          \
        float x0, y0, x1, y1;                                                      \
        upk2(add2_(c0a, c0b), x0, y0);                                             \
        upk2(add2_(c1a, c1b), x1, y1);                                             \
        float acc0 = x0 + y0;                                                      \
        float acc1 = x1 + y1;                                                      \
        acc0 += __shfl_xor_sync(0xffffffffu, acc0, 1);                             \
        acc1 += __shfl_xor_sync(0xffffffffu, acc1, 1);                             \
        acc0 += __shfl_xor_sync(0xffffffffu, acc0, 2);                             \
        acc1 += __shfl_xor_sync(0xffffffffu, acc1, 2);                             \
        const float un0 = (FOLD) ? acc0 * (p0 * sc_) : acc0 * p0;                  \
        const float un1 = (FOLD) ? acc1 * (p1 * sc_) : acc1 * p1;                  \
        if (PUB) {                                                                 \
            const int im = __reduce_max_sync(0xffffffffu,                          \
                                 __float_as_int(fmaxf(un0, un1)));                 \
            if ((tid & 31) == 0) wm[warp] = __int_as_float(im);                    \
        }                                                                          \
        if (ich == 0) {                                                            \
            float2 w; w.x = un0; w.y = un1;                                        \
            *reinterpret_cast<float2*>(&v_sm[(CBUF) ^ 1][wslot]) = w;              \
        }                                                                          \
        __syncthreads();                                                           \
    }

    // ---- full 8-step groups: t0 = 1, 9, 17, ...  (t0 % 8 == 1) ----
    int t0 = 1;
    for (; t0 + 7 < T; t0 += 8) {
        CRF_STEP(t0 + 0, 0, true,  false)   // t%8==1: fold
        CRF_STEP(t0 + 1, 1, false, false)
        CRF_STEP(t0 + 2, 0, false, false)
        CRF_STEP(t0 + 3, 1, false, false)
        CRF_STEP(t0 + 4, 0, false, false)
        CRF_STEP(t0 + 5, 1, false, false)
        CRF_STEP(t0 + 6, 0, false, false)
        CRF_STEP(t0 + 7, 1, false, true)    // t%8==0: publish
    }
    // ---- tail: general fold/publish on (t & 7) ----
    for (int t = t0; t < T; ++t) {
        const int cb = (t - 1) & 1;
        const bool fold = (t & 7) == 1;
        const bool pub  = (t & 7) == 0;
        CRF_STEP(t, cb, fold, pub)
    }
#undef CRF_STEP

    // ---- finalize: out[b] = -ln2 * (log2(sum_j v_j) + L) ----
    const int fb = (T - 1) & 1;
    float vv = 0.f;
    if (tid < 128) vv = v_sm[fb][((tid >> 5) * CH) + (tid & 31)];
#pragma unroll
    for (int o = 16; o; o >>= 1) vv += __shfl_xor_sync(0xffffffffu, vv, o);
    if (tid < 128 && (tid & 31) == 0) wsum[tid >> 5] = vv;
    __syncthreads();
    if (tid == 0) {
        const float s = (wsum[0] + wsum[1]) + (wsum[2] + wsum[3]);
        out[b] = -LN2_F * (lg2f_(s) + (float)L);
    }
}

extern "C" void kernel_launch(void* const* d_in, const int* in_sizes, int n_in,
                              void* d_out, int out_size)
{
    const float* obs  = (const float*)d_in[0];   // [B, T, S] f32
    const float* logA = (const float*)d_in[1];   // [S, S]   f32
    float* out = (float*)d_out;                  // [B]      f32

    const int B = out_size;
    const int S = 128;
    const int T = in_sizes[0] / (B * S);

    crf_fwd_kernel<<<B, 256>>>(obs, logA, out, T);
}